// round 3
// baseline (speedup 1.0000x reference)
#include <cuda_runtime.h>
#include <math.h>

#define BC   64
#define H    512
#define W    512
#define OH   170
#define OW   170
#define OHW  (OH*OW)     // 28900
#define NH   168
#define NW   168
#define NPOS (NH*NW)     // 28224
#define RES  2044        // residual BCE elements per bc (rows 510-511 full + cols 510-511 partial)
#define EPSI 0.0005f
#define G2   4           // row-chunks per (b,c) in cov kernels

// -------- device scratch (static, allocation-free) --------
__device__ float g_pd[BC*OHW];      // pooled sigmoid(pred)
__device__ float g_td[BC*OHW];      // pooled target
__device__ float g_bce;             // BCE sum accumulator
__device__ float g_means[BC][18];   // [0..8] target means, [9..17] pred means
__device__ float g_cov[BC][171];    // 0..44 y_cov(ut), 45..89 p_cov(ut), 90..170 y_p_cov(full)

// -------- init: zero accumulators each replay --------
__global__ void zero_kernel() {
    int i = blockIdx.x * blockDim.x + threadIdx.x;
    if (i == 0) g_bce = 0.f;
    if (i < BC*171) ((float*)g_cov)[i] = 0.f;
}

__device__ __forceinline__ float bce_term(float x, float t) {
    // -(t*log(sigmoid(x)) + (1-t)*log(1-sigmoid(x))) , numerically stable
    return fmaxf(x, 0.f) - x*t + log1pf(expf(-fabsf(x)));
}

// -------- stage 1: fused sigmoid + BCE + 3x3/3 avg-pool --------
__global__ void __launch_bounds__(256) stage1(const float* __restrict__ pred,
                                              const float* __restrict__ target) {
    const int bc  = blockIdx.y;
    const int idx = blockIdx.x * 256 + threadIdx.x;
    const float* __restrict__ pb = pred   + (size_t)bc * (H*W);
    const float* __restrict__ tb = target + (size_t)bc * (H*W);

    float bce = 0.f;
    if (idx < OHW) {
        const int oy = idx / OW, ox = idx % OW;
        const float* pp = pb + (oy*3)*W + ox*3;
        const float* tp = tb + (oy*3)*W + ox*3;
        float ps = 0.f, ts = 0.f;
        #pragma unroll
        for (int dy = 0; dy < 3; dy++) {
            #pragma unroll
            for (int dx = 0; dx < 3; dx++) {
                float x = pp[dy*W + dx];
                float t = tp[dy*W + dx];
                ps += 1.f / (1.f + expf(-x));
                ts += t;
                bce += bce_term(x, t);
            }
        }
        g_pd[bc*OHW + idx] = ps * (1.f/9.f);
        g_td[bc*OHW + idx] = ts * (1.f/9.f);
    } else {
        int j = idx - OHW;
        if (j < RES) {
            int y, x;
            if (j < 1024) { y = 510 + (j >> 9); x = j & 511; }           // rows 510,511 all cols
            else          { int k = j - 1024; y = k >> 1; x = 510 + (k & 1); } // cols 510,511 rows 0..509
            float xv = pb[y*W + x];
            float tv = tb[y*W + x];
            bce = bce_term(xv, tv);
        }
    }

    // block reduction of bce
    __shared__ float red[8];
    #pragma unroll
    for (int o = 16; o; o >>= 1) bce += __shfl_xor_sync(0xffffffffu, bce, o);
    if ((threadIdx.x & 31) == 0) red[threadIdx.x >> 5] = bce;
    __syncthreads();
    if (threadIdx.x < 8) {
        float v = red[threadIdx.x];
        #pragma unroll
        for (int o = 4; o; o >>= 1) v += __shfl_xor_sync(0xffu, v, o);
        if (threadIdx.x == 0) atomicAdd(&g_bce, v);
    }
}

// -------- stage 1.5: per-(b,c) means of the 9 shifted 168x168 windows --------
__global__ void __launch_bounds__(256) means_kernel() {
    const int bc = blockIdx.x;
    const float* __restrict__ td = g_td + bc*OHW;
    const float* __restrict__ pd = g_pd + bc*OHW;
    float at[9], ap[9];
    #pragma unroll
    for (int k = 0; k < 9; k++) { at[k] = 0.f; ap[k] = 0.f; }

    for (int i = threadIdx.x; i < OHW; i += 256) {
        const int y = i / OW, x = i % OW;
        const float tv = td[i], pv = pd[i];
        #pragma unroll
        for (int ry = 0; ry < 3; ry++) {
            const bool oky = (y >= ry) && (y - ry < NH);
            #pragma unroll
            for (int rx = 0; rx < 3; rx++) {
                const bool okx = (x >= rx) && (x - rx < NW);
                if (oky && okx) { at[ry*3+rx] += tv; ap[ry*3+rx] += pv; }
            }
        }
    }

    __shared__ float s[18];
    if (threadIdx.x < 18) s[threadIdx.x] = 0.f;
    __syncthreads();
    #pragma unroll
    for (int k = 0; k < 9; k++) {
        float v = at[k];
        #pragma unroll
        for (int o = 16; o; o >>= 1) v += __shfl_xor_sync(0xffffffffu, v, o);
        if ((threadIdx.x & 31) == 0) atomicAdd(&s[k], v);
        float w = ap[k];
        #pragma unroll
        for (int o = 16; o; o >>= 1) w += __shfl_xor_sync(0xffffffffu, w, o);
        if ((threadIdx.x & 31) == 0) atomicAdd(&s[9+k], w);
    }
    __syncthreads();
    if (threadIdx.x < 18) g_means[bc][threadIdx.x] = s[threadIdx.x] * (1.f/(float)NPOS);
}

// Each thread handles TWO adjacent positions (2*tid, 2*tid+1) within a row
// chunk: the 3x3 windows at ix and ix+1 overlap in 2 of 3 columns, so the
// second position needs only 6 fresh loads instead of 18.
#define POS_PER_ROW_HALF (NW/2)   // 84 position-pairs per row

// -------- stage 2a: symmetric covariances (y_cov, p_cov) --------
__global__ void __launch_bounds__(256, 1) cov_sym() {
    const int bc = blockIdx.y;
    const float* __restrict__ td = g_td + bc*OHW;
    const float* __restrict__ pd = g_pd + bc*OHW;

    float my[9], mp[9];
    #pragma unroll
    for (int k = 0; k < 9; k++) { my[k] = g_means[bc][k]; mp[k] = g_means[bc][9+k]; }

    float ayy[45], app[45];
    #pragma unroll
    for (int k = 0; k < 45; k++) { ayy[k] = 0.f; app[k] = 0.f; }

    const int rows_per = (NH + G2 - 1) / G2;            // 42 rows per block
    const int r0 = blockIdx.x * rows_per;
    const int npair0 = r0 * POS_PER_ROW_HALF;
    const int npair1 = min(r0 + rows_per, NH) * POS_PER_ROW_HALF;

    for (int pp = npair0 + (int)threadIdx.x; pp < npair1; pp += 256) {
        const int iy = pp / POS_PER_ROW_HALF;
        const int ix = (pp % POS_PER_ROW_HALF) * 2;
        float ty[12], tp[12];
        #pragma unroll
        for (int ry = 0; ry < 3; ry++) {
            const int o = (iy + ry)*OW + ix;
            #pragma unroll
            for (int rx = 0; rx < 4; rx++) {
                ty[ry*4+rx] = __ldg(td + o + rx);
                tp[ry*4+rx] = __ldg(pd + o + rx);
            }
        }
        #pragma unroll
        for (int sh = 0; sh < 2; sh++) {
            float yv[9], pv[9];
            #pragma unroll
            for (int ry = 0; ry < 3; ry++)
                #pragma unroll
                for (int rx = 0; rx < 3; rx++) {
                    yv[ry*3+rx] = ty[ry*4+rx+sh] - my[ry*3+rx];
                    pv[ry*3+rx] = tp[ry*4+rx+sh] - mp[ry*3+rx];
                }
            int c = 0;
            #pragma unroll
            for (int r = 0; r < 9; r++)
                #pragma unroll
                for (int s = r; s < 9; s++, c++) {
                    ayy[c] += yv[r]*yv[s];
                    app[c] += pv[r]*pv[s];
                }
        }
    }

    const int lane = threadIdx.x & 31;
    #pragma unroll
    for (int k = 0; k < 45; k++) {
        float v = ayy[k];
        #pragma unroll
        for (int o = 16; o; o >>= 1) v += __shfl_xor_sync(0xffffffffu, v, o);
        if (lane == (k & 31)) atomicAdd(&g_cov[bc][k], v);
    }
    #pragma unroll
    for (int k = 0; k < 45; k++) {
        float v = app[k];
        #pragma unroll
        for (int o = 16; o; o >>= 1) v += __shfl_xor_sync(0xffffffffu, v, o);
        if (lane == (k & 31)) atomicAdd(&g_cov[bc][45 + k], v);
    }
}

// -------- stage 2b: cross covariance (y_p_cov) --------
__global__ void __launch_bounds__(256, 1) cov_cross() {
    const int bc = blockIdx.y;
    const float* __restrict__ td = g_td + bc*OHW;
    const float* __restrict__ pd = g_pd + bc*OHW;

    float my[9], mp[9];
    #pragma unroll
    for (int k = 0; k < 9; k++) { my[k] = g_means[bc][k]; mp[k] = g_means[bc][9+k]; }

    float ayp[81];
    #pragma unroll
    for (int k = 0; k < 81; k++) ayp[k] = 0.f;

    const int rows_per = (NH + G2 - 1) / G2;
    const int r0 = blockIdx.x * rows_per;
    const int npair0 = r0 * POS_PER_ROW_HALF;
    const int npair1 = min(r0 + rows_per, NH) * POS_PER_ROW_HALF;

    for (int pp = npair0 + (int)threadIdx.x; pp < npair1; pp += 256) {
        const int iy = pp / POS_PER_ROW_HALF;
        const int ix = (pp % POS_PER_ROW_HALF) * 2;
        float ty[12], tp[12];
        #pragma unroll
        for (int ry = 0; ry < 3; ry++) {
            const int o = (iy + ry)*OW + ix;
            #pragma unroll
            for (int rx = 0; rx < 4; rx++) {
                ty[ry*4+rx] = __ldg(td + o + rx);
                tp[ry*4+rx] = __ldg(pd + o + rx);
            }
        }
        #pragma unroll
        for (int sh = 0; sh < 2; sh++) {
            float yv[9], pv[9];
            #pragma unroll
            for (int ry = 0; ry < 3; ry++)
                #pragma unroll
                for (int rx = 0; rx < 3; rx++) {
                    yv[ry*3+rx] = ty[ry*4+rx+sh] - my[ry*3+rx];
                    pv[ry*3+rx] = tp[ry*4+rx+sh] - mp[ry*3+rx];
                }
            #pragma unroll
            for (int r = 0; r < 9; r++)
                #pragma unroll
                for (int s = 0; s < 9; s++)
                    ayp[r*9+s] += yv[r]*pv[s];
        }
    }

    const int lane = threadIdx.x & 31;
    #pragma unroll
    for (int k = 0; k < 81; k++) {
        float v = ayp[k];
        #pragma unroll
        for (int o = 16; o; o >>= 1) v += __shfl_xor_sync(0xffffffffu, v, o);
        if (lane == (k & 31)) atomicAdd(&g_cov[bc][90 + k], v);
    }
}

// -------- stage 3: 64 tiny 9x9 solves + logdet + final combine --------
__global__ void __launch_bounds__(64) stage3(float* __restrict__ out) {
    const int bc = threadIdx.x;   // 0..63
    const float* cv = g_cov[bc];

    float Ym[9][9], P[9][9], Cm[9][9];
    int c = 0;
    for (int r = 0; r < 9; r++)
        for (int s = r; s < 9; s++, c++) { Ym[r][s] = cv[c]; Ym[s][r] = cv[c]; }
    for (int r = 0; r < 9; r++)
        for (int s = r; s < 9; s++, c++) { P[r][s] = cv[c]; P[s][r] = cv[c]; }
    for (int r = 0; r < 9; r++)
        for (int s = 0; s < 9; s++, c++) Cm[r][s] = cv[c];
    for (int r = 0; r < 9; r++) P[r][r] += EPSI;

    // Cholesky P = L L^T (L stored in lower triangle of P)
    for (int k = 0; k < 9; k++) {
        float d = P[k][k];
        for (int j = 0; j < k; j++) d -= P[k][j]*P[k][j];
        d = sqrtf(d);
        P[k][k] = d;
        const float inv = 1.f / d;
        for (int i = k + 1; i < 9; i++) {
            float v = P[i][k];
            for (int j = 0; j < k; j++) v -= P[i][j]*P[k][j];
            P[i][k] = v * inv;
        }
    }

    // U[i][:] = L^{-1} c_i  where c_i = row i of Cm  =>  C P^{-1} C^T = U U^T
    float U[9][9];
    for (int i = 0; i < 9; i++) {
        for (int k = 0; k < 9; k++) {
            float v = Cm[i][k];
            for (int j = 0; j < k; j++) v -= P[k][j]*U[i][j];
            U[i][k] = v / P[k][k];
        }
    }

    // M = Y - U U^T + eps I ; logdet via Cholesky
    float M[9][9];
    for (int i = 0; i < 9; i++)
        for (int j = 0; j < 9; j++) {
            float v = Ym[i][j];
            for (int k = 0; k < 9; k++) v -= U[i][k]*U[j][k];
            M[i][j] = v;
        }
    for (int i = 0; i < 9; i++) M[i][i] += EPSI;

    float logdet = 0.f;
    for (int k = 0; k < 9; k++) {
        float d = M[k][k];
        for (int j = 0; j < k; j++) d -= M[k][j]*M[k][j];
        d = sqrtf(d);
        logdet += 2.f * logf(d);
        M[k][k] = d;
        const float inv = 1.f / d;
        for (int i = k + 1; i < 9; i++) {
            float v = M[i][k];
            for (int j = 0; j < k; j++) v -= M[i][j]*M[k][j];
            M[i][k] = v * inv;
        }
    }

    // rmi per (b,c) = 0.5 * (2*logdet) / 9 = logdet/9
    float val = logdet * (1.f/9.f);
    #pragma unroll
    for (int o = 16; o; o >>= 1) val += __shfl_xor_sync(0xffffffffu, val, o);
    __shared__ float s2[2];
    if ((threadIdx.x & 31) == 0) s2[threadIdx.x >> 5] = val;
    __syncthreads();
    if (threadIdx.x == 0) {
        const float rmi = (s2[0] + s2[1]) * (1.f/8.f);      // sum over c, mean over b
        const float bce_mean = g_bce * (1.f/16777216.0f);
        out[0] = 0.5f * rmi + 0.5f * bce_mean;
    }
}

extern "C" void kernel_launch(void* const* d_in, const int* in_sizes, int n_in,
                              void* d_out, int out_size) {
    const float* pred   = (const float*)d_in[0];
    const float* target = (const float*)d_in[1];
    float* out = (float*)d_out;

    zero_kernel<<<43, 256>>>();                 // 43*256 >= 64*171+1

    dim3 g1((OHW + RES + 255) / 256, BC);       // 121 x 64
    stage1<<<g1, 256>>>(pred, target);

    means_kernel<<<BC, 256>>>();

    dim3 g2(G2, BC);                            // 4 x 64
    cov_sym<<<g2, 256>>>();
    cov_cross<<<g2, 256>>>();

    stage3<<<1, 64>>>(out);
}

// round 4
// speedup vs baseline: 1.9569x; 1.9569x over previous
#include <cuda_runtime.h>
#include <math.h>

#define BC    64
#define H     512
#define W     512
#define OH    170
#define OW    170
#define OWP   172            // padded row stride (divisible by 4 -> float4 aligned)
#define OHWP  (OH*OWP)
#define OHW   (OH*OW)
#define NH    168
#define NW    168
#define NPOS  (NH*NW)        // 28224
#define RES   2044
#define EPSI  0.0005f

// -------- device scratch (static, allocation-free) --------
__device__ float g_pd[BC*OHWP];     // pooled sigmoid(pred), padded rows
__device__ float g_td[BC*OHWP];     // pooled target, padded rows
__device__ float g_bce;             // BCE sum
__device__ float g_means[BC][18];   // RAW window sums: [0..8] target, [9..17] pred
__device__ float g_cov[BC][171];    // 0..44 y_cov(ut), 45..89 p_cov(ut), 90..170 y_p_cov

// -------- init --------
__global__ void zero_kernel() {
    int i = blockIdx.x * blockDim.x + threadIdx.x;
    if (i == 0) g_bce = 0.f;
    if (i < BC*171) ((float*)g_cov)[i] = 0.f;
    if (i < BC*18)  ((float*)g_means)[i] = 0.f;
}

// -------- stage 1: fused sigmoid + BCE + 3x3/3 avg-pool (fast math) --------
__global__ void __launch_bounds__(256) stage1(const float* __restrict__ pred,
                                              const float* __restrict__ target) {
    const int bc  = blockIdx.y;
    const int idx = blockIdx.x * 256 + threadIdx.x;
    const float* __restrict__ pb = pred   + (size_t)bc * (H*W);
    const float* __restrict__ tb = target + (size_t)bc * (H*W);

    float bce = 0.f;
    if (idx < OHW) {
        const int oy = idx / OW, ox = idx % OW;
        const float* pp = pb + (oy*3)*W + ox*3;
        const float* tp = tb + (oy*3)*W + ox*3;
        float ps = 0.f, ts = 0.f;
        #pragma unroll
        for (int dy = 0; dy < 3; dy++) {
            #pragma unroll
            for (int dx = 0; dx < 3; dx++) {
                const float x = pp[dy*W + dx];
                const float t = tp[dy*W + dx];
                const float e = __expf(-fabsf(x));
                const float r = __fdividef(1.f, 1.f + e);
                ps += (x >= 0.f) ? r : e * r;              // sigmoid(x)
                ts += t;
                bce += fmaxf(x, 0.f) - x*t + __logf(1.f + e);
            }
        }
        g_pd[bc*OHWP + oy*OWP + ox] = ps * (1.f/9.f);
        g_td[bc*OHWP + oy*OWP + ox] = ts * (1.f/9.f);
    } else {
        int j = idx - OHW;
        if (j < RES) {
            int y, x;
            if (j < 1024) { y = 510 + (j >> 9); x = j & 511; }
            else          { int k = j - 1024; y = k >> 1; x = 510 + (k & 1); }
            const float xv = pb[y*W + x];
            const float tv = tb[y*W + x];
            const float e = __expf(-fabsf(xv));
            bce = fmaxf(xv, 0.f) - xv*tv + __logf(1.f + e);
        }
    }

    __shared__ float red[8];
    #pragma unroll
    for (int o = 16; o; o >>= 1) bce += __shfl_xor_sync(0xffffffffu, bce, o);
    if ((threadIdx.x & 31) == 0) red[threadIdx.x >> 5] = bce;
    __syncthreads();
    if (threadIdx.x < 8) {
        float v = red[threadIdx.x];
        #pragma unroll
        for (int o = 4; o; o >>= 1) v += __shfl_xor_sync(0xffu, v, o);
        if (threadIdx.x == 0) atomicAdd(&g_bce, v);
    }
}

// -------- stage 1.5: raw window sums (parallel over 4 row-chunks) --------
__global__ void __launch_bounds__(256) means_kernel() {
    const int bc = blockIdx.y;
    const int row0 = blockIdx.x * 43;
    const int rows = min(43, OH - row0);
    const float* __restrict__ td = g_td + bc*OHWP;
    const float* __restrict__ pd = g_pd + bc*OHWP;

    float at[9], ap[9];
    #pragma unroll
    for (int k = 0; k < 9; k++) { at[k] = 0.f; ap[k] = 0.f; }

    for (int i = threadIdx.x; i < rows*OW; i += 256) {
        const int y = row0 + i / OW, x = i % OW;
        const float tv = td[y*OWP + x], pv = pd[y*OWP + x];
        #pragma unroll
        for (int ry = 0; ry < 3; ry++) {
            const bool oky = (y >= ry) && (y - ry < NH);
            #pragma unroll
            for (int rx = 0; rx < 3; rx++) {
                const bool okx = (x >= rx) && (x - rx < NW);
                if (oky && okx) { at[ry*3+rx] += tv; ap[ry*3+rx] += pv; }
            }
        }
    }

    __shared__ float s[18];
    if (threadIdx.x < 18) s[threadIdx.x] = 0.f;
    __syncthreads();
    #pragma unroll
    for (int k = 0; k < 9; k++) {
        float v = at[k];
        #pragma unroll
        for (int o = 16; o; o >>= 1) v += __shfl_xor_sync(0xffffffffu, v, o);
        if ((threadIdx.x & 31) == 0) atomicAdd(&s[k], v);
        float w = ap[k];
        #pragma unroll
        for (int o = 16; o; o >>= 1) w += __shfl_xor_sync(0xffffffffu, w, o);
        if ((threadIdx.x & 31) == 0) atomicAdd(&s[9+k], w);
    }
    __syncthreads();
    if (threadIdx.x < 18) atomicAdd(&g_means[bc][threadIdx.x], s[threadIdx.x]);
}

// -------- block reduction helper --------
template<int NA>
__device__ __forceinline__ void reduce_atomic(float* acc, float* gdst, float (*sred)[45]) {
    const int wid = threadIdx.x >> 5, lane = threadIdx.x & 31;
    #pragma unroll
    for (int k = 0; k < NA; k++) {
        float v = acc[k];
        #pragma unroll
        for (int o = 16; o; o >>= 1) v += __shfl_xor_sync(0xffffffffu, v, o);
        if (lane == 0) sred[wid][k] = v;
    }
    __syncthreads();
    if (threadIdx.x < NA) {
        float s = 0.f;
        #pragma unroll
        for (int w = 0; w < 8; w++) s += sred[w][threadIdx.x];
        atomicAdd(&gdst[threadIdx.x], s);
    }
}

// -------- stage 2: covariances. gridDim.x = 16 (4 row-chunks x 4 parts) --------
__global__ void __launch_bounds__(256, 2) cov_kernel() {
    const int part  = blockIdx.x & 3;
    const int chunk = blockIdx.x >> 2;
    const int bc    = blockIdx.y;
    const float* __restrict__ td = g_td + bc*OHWP;
    const float* __restrict__ pd = g_pd + bc*OHWP;
    __shared__ float sred[8][45];
    const float inv_n = 1.f/(float)NPOS;
    const int row0 = chunk * 42;                 // 4 chunks x 42 rows = 168
    const int NIT  = 42*42;                      // groups per chunk (4 positions each)

    if (part == 0) {            // ---- y_cov (45 upper-tri) ----
        float my[9];
        #pragma unroll
        for (int k = 0; k < 9; k++) my[k] = g_means[bc][k] * inv_n;
        float acc[45];
        #pragma unroll
        for (int k = 0; k < 45; k++) acc[k] = 0.f;

        for (int it = threadIdx.x; it < NIT; it += 256) {
            const int iy = row0 + it / 42, ix0 = (it % 42) * 4;
            float ty[18];
            #pragma unroll
            for (int ry = 0; ry < 3; ry++) {
                const float* b = td + (iy+ry)*OWP + ix0;
                const float4 a = *(const float4*)b;
                const float2 c2 = *(const float2*)(b+4);
                ty[ry*6+0]=a.x; ty[ry*6+1]=a.y; ty[ry*6+2]=a.z;
                ty[ry*6+3]=a.w; ty[ry*6+4]=c2.x; ty[ry*6+5]=c2.y;
            }
            #pragma unroll
            for (int sh = 0; sh < 4; sh++) {
                float yv[9];
                #pragma unroll
                for (int ry = 0; ry < 3; ry++)
                    #pragma unroll
                    for (int rx = 0; rx < 3; rx++)
                        yv[ry*3+rx] = ty[ry*6+rx+sh] - my[ry*3+rx];
                int c = 0;
                #pragma unroll
                for (int r = 0; r < 9; r++)
                    #pragma unroll
                    for (int s = r; s < 9; s++, c++) acc[c] += yv[r]*yv[s];
            }
        }
        reduce_atomic<45>(acc, &g_cov[bc][0], sred);

    } else if (part == 1) {     // ---- p_cov (45 upper-tri) ----
        float mp[9];
        #pragma unroll
        for (int k = 0; k < 9; k++) mp[k] = g_means[bc][9+k] * inv_n;
        float acc[45];
        #pragma unroll
        for (int k = 0; k < 45; k++) acc[k] = 0.f;

        for (int it = threadIdx.x; it < NIT; it += 256) {
            const int iy = row0 + it / 42, ix0 = (it % 42) * 4;
            float tp[18];
            #pragma unroll
            for (int ry = 0; ry < 3; ry++) {
                const float* b = pd + (iy+ry)*OWP + ix0;
                const float4 a = *(const float4*)b;
                const float2 c2 = *(const float2*)(b+4);
                tp[ry*6+0]=a.x; tp[ry*6+1]=a.y; tp[ry*6+2]=a.z;
                tp[ry*6+3]=a.w; tp[ry*6+4]=c2.x; tp[ry*6+5]=c2.y;
            }
            #pragma unroll
            for (int sh = 0; sh < 4; sh++) {
                float pv[9];
                #pragma unroll
                for (int ry = 0; ry < 3; ry++)
                    #pragma unroll
                    for (int rx = 0; rx < 3; rx++)
                        pv[ry*3+rx] = tp[ry*6+rx+sh] - mp[ry*3+rx];
                int c = 0;
                #pragma unroll
                for (int r = 0; r < 9; r++)
                    #pragma unroll
                    for (int s = r; s < 9; s++, c++) acc[c] += pv[r]*pv[s];
            }
        }
        reduce_atomic<45>(acc, &g_cov[bc][45], sred);

    } else if (part == 2) {     // ---- y_p_cov rows 0..4 (45) ----
        float my[6], mp[9];
        #pragma unroll
        for (int k = 0; k < 6; k++) my[k] = g_means[bc][k] * inv_n;
        #pragma unroll
        for (int k = 0; k < 9; k++) mp[k] = g_means[bc][9+k] * inv_n;
        float acc[45];
        #pragma unroll
        for (int k = 0; k < 45; k++) acc[k] = 0.f;

        for (int it = threadIdx.x; it < NIT; it += 256) {
            const int iy = row0 + it / 42, ix0 = (it % 42) * 4;
            float ty[12], tp[18];
            #pragma unroll
            for (int ry = 0; ry < 2; ry++) {         // y rows 0..1 cover r=0..5
                const float* b = td + (iy+ry)*OWP + ix0;
                const float4 a = *(const float4*)b;
                const float2 c2 = *(const float2*)(b+4);
                ty[ry*6+0]=a.x; ty[ry*6+1]=a.y; ty[ry*6+2]=a.z;
                ty[ry*6+3]=a.w; ty[ry*6+4]=c2.x; ty[ry*6+5]=c2.y;
            }
            #pragma unroll
            for (int ry = 0; ry < 3; ry++) {
                const float* b = pd + (iy+ry)*OWP + ix0;
                const float4 a = *(const float4*)b;
                const float2 c2 = *(const float2*)(b+4);
                tp[ry*6+0]=a.x; tp[ry*6+1]=a.y; tp[ry*6+2]=a.z;
                tp[ry*6+3]=a.w; tp[ry*6+4]=c2.x; tp[ry*6+5]=c2.y;
            }
            #pragma unroll
            for (int sh = 0; sh < 4; sh++) {
                float yv[5], pv[9];
                #pragma unroll
                for (int r = 0; r < 5; r++)          // (ry,rx) = (r/3, r%3)
                    yv[r] = ty[(r/3)*6 + (r%3) + sh] - my[r];
                #pragma unroll
                for (int s = 0; s < 9; s++)
                    pv[s] = tp[(s/3)*6 + (s%3) + sh] - mp[s];
                #pragma unroll
                for (int r = 0; r < 5; r++)
                    #pragma unroll
                    for (int s = 0; s < 9; s++) acc[r*9+s] += yv[r]*pv[s];
            }
        }
        reduce_atomic<45>(acc, &g_cov[bc][90], sred);

    } else {                    // ---- y_p_cov rows 5..8 (36) ----
        float my[4], mp[9];
        #pragma unroll
        for (int k = 0; k < 4; k++) my[k] = g_means[bc][5+k] * inv_n;
        #pragma unroll
        for (int k = 0; k < 9; k++) mp[k] = g_means[bc][9+k] * inv_n;
        float acc[36];
        #pragma unroll
        for (int k = 0; k < 36; k++) acc[k] = 0.f;

        for (int it = threadIdx.x; it < NIT; it += 256) {
            const int iy = row0 + it / 42, ix0 = (it % 42) * 4;
            float ty[12], tp[18];
            #pragma unroll
            for (int lr = 0; lr < 2; lr++) {         // y rows 1..2 cover r=3..8
                const float* b = td + (iy+1+lr)*OWP + ix0;
                const float4 a = *(const float4*)b;
                const float2 c2 = *(const float2*)(b+4);
                ty[lr*6+0]=a.x; ty[lr*6+1]=a.y; ty[lr*6+2]=a.z;
                ty[lr*6+3]=a.w; ty[lr*6+4]=c2.x; ty[lr*6+5]=c2.y;
            }
            #pragma unroll
            for (int ry = 0; ry < 3; ry++) {
                const float* b = pd + (iy+ry)*OWP + ix0;
                const float4 a = *(const float4*)b;
                const float2 c2 = *(const float2*)(b+4);
                tp[ry*6+0]=a.x; tp[ry*6+1]=a.y; tp[ry*6+2]=a.z;
                tp[ry*6+3]=a.w; tp[ry*6+4]=c2.x; tp[ry*6+5]=c2.y;
            }
            #pragma unroll
            for (int sh = 0; sh < 4; sh++) {
                float yv[4], pv[9];
                #pragma unroll
                for (int q = 0; q < 4; q++) {        // r = 5+q ; (ry,rx)=((5+q)/3,(5+q)%3), local row = ry-1
                    const int r = 5 + q;
                    yv[q] = ty[(r/3 - 1)*6 + (r%3) + sh] - my[q];
                }
                #pragma unroll
                for (int s = 0; s < 9; s++)
                    pv[s] = tp[(s/3)*6 + (s%3) + sh] - mp[s];
                #pragma unroll
                for (int q = 0; q < 4; q++)
                    #pragma unroll
                    for (int s = 0; s < 9; s++) acc[q*9+s] += yv[q]*pv[s];
            }
        }
        reduce_atomic<36>(acc, &g_cov[bc][135], sred);
    }
}

// -------- stage 3: 64 tiny 9x9 solves + logdet + final combine --------
__global__ void __launch_bounds__(64) stage3(float* __restrict__ out) {
    const int bc = threadIdx.x;
    const float* cv = g_cov[bc];

    float Ym[9][9], P[9][9], Cm[9][9];
    int c = 0;
    for (int r = 0; r < 9; r++)
        for (int s = r; s < 9; s++, c++) { Ym[r][s] = cv[c]; Ym[s][r] = cv[c]; }
    for (int r = 0; r < 9; r++)
        for (int s = r; s < 9; s++, c++) { P[r][s] = cv[c]; P[s][r] = cv[c]; }
    for (int r = 0; r < 9; r++)
        for (int s = 0; s < 9; s++, c++) Cm[r][s] = cv[c];
    for (int r = 0; r < 9; r++) P[r][r] += EPSI;

    for (int k = 0; k < 9; k++) {           // Cholesky P = L L^T
        float d = P[k][k];
        for (int j = 0; j < k; j++) d -= P[k][j]*P[k][j];
        d = sqrtf(d);
        P[k][k] = d;
        const float inv = 1.f / d;
        for (int i = k + 1; i < 9; i++) {
            float v = P[i][k];
            for (int j = 0; j < k; j++) v -= P[i][j]*P[k][j];
            P[i][k] = v * inv;
        }
    }

    float U[9][9];                          // U = C L^{-T}; C P^{-1} C^T = U U^T
    for (int i = 0; i < 9; i++) {
        for (int k = 0; k < 9; k++) {
            float v = Cm[i][k];
            for (int j = 0; j < k; j++) v -= P[k][j]*U[i][j];
            U[i][k] = v / P[k][k];
        }
    }

    float M[9][9];
    for (int i = 0; i < 9; i++)
        for (int j = 0; j < 9; j++) {
            float v = Ym[i][j];
            for (int k = 0; k < 9; k++) v -= U[i][k]*U[j][k];
            M[i][j] = v;
        }
    for (int i = 0; i < 9; i++) M[i][i] += EPSI;

    float logdet = 0.f;
    for (int k = 0; k < 9; k++) {
        float d = M[k][k];
        for (int j = 0; j < k; j++) d -= M[k][j]*M[k][j];
        d = sqrtf(d);
        logdet += 2.f * logf(d);
        M[k][k] = d;
        const float inv = 1.f / d;
        for (int i = k + 1; i < 9; i++) {
            float v = M[i][k];
            for (int j = 0; j < k; j++) v -= M[i][j]*M[k][j];
            M[i][k] = v * inv;
        }
    }

    float val = logdet * (1.f/9.f);
    #pragma unroll
    for (int o = 16; o; o >>= 1) val += __shfl_xor_sync(0xffffffffu, val, o);
    __shared__ float s2[2];
    if ((threadIdx.x & 31) == 0) s2[threadIdx.x >> 5] = val;
    __syncthreads();
    if (threadIdx.x == 0) {
        const float rmi = (s2[0] + s2[1]) * (1.f/8.f);
        const float bce_mean = g_bce * (1.f/16777216.0f);
        out[0] = 0.5f * rmi + 0.5f * bce_mean;
    }
}

extern "C" void kernel_launch(void* const* d_in, const int* in_sizes, int n_in,
                              void* d_out, int out_size) {
    const float* pred   = (const float*)d_in[0];
    const float* target = (const float*)d_in[1];
    float* out = (float*)d_out;

    zero_kernel<<<48, 256>>>();

    dim3 g1((OHW + RES + 255) / 256, BC);       // 121 x 64
    stage1<<<g1, 256>>>(pred, target);

    dim3 gm(4, BC);
    means_kernel<<<gm, 256>>>();

    dim3 g2(16, BC);                            // 4 chunks x 4 parts, 64 bc
    cov_kernel<<<g2, 256>>>();

    stage3<<<1, 64>>>(out);
}